// round 11
// baseline (speedup 1.0000x reference)
#include <cuda_runtime.h>
#include <math.h>

#define DIM 128
#define NMAX 50000
#define EMAX 800000
#define ELLW 96                             // max in-degree slots per node (Poisson(16) tail-safe)

// Scratch (no allocs allowed)
__device__ float g_h[(size_t)NMAX * DIM];   // h = LN(x) @ W^T
__device__ float g_deg[NMAX];
__device__ float g_dinv[NMAX];
__device__ int   g_count[NMAX];
__device__ int2  g_ell[(size_t)NMAX * ELLW]; // (src, ew-as-int) per ELL slot
__device__ unsigned long long g_Wdup[DIM * DIM]; // (w,w) packed f32x2 copy of W
__device__ int   g_is64;

__device__ __forceinline__ int edge_idx(const void* ei, int is64, size_t pos) {
    return is64 ? (int)((const long long*)ei)[pos] : ((const int*)ei)[pos];
}

// ---------------------------------------------------------------------------
// f32x2 packed-FMA helpers (FFMA2 is PTX-only on sm_103a)
// ---------------------------------------------------------------------------
__device__ __forceinline__ void ffma2(unsigned long long& acc,
                                      unsigned long long a, unsigned long long b) {
    asm("fma.rn.f32x2 %0, %1, %2, %0;" : "+l"(acc) : "l"(a), "l"(b));
}
__device__ __forceinline__ unsigned long long pk2(float lo, float hi) {
    unsigned long long r;
    asm("mov.b64 %0, {%1, %2};" : "=l"(r) : "f"(lo), "f"(hi));
    return r;
}
__device__ __forceinline__ float2 upk2(unsigned long long v) {
    float2 r;
    asm("mov.b64 {%0, %1}, %2;" : "=f"(r.x), "=f"(r.y) : "l"(v));
    return r;
}

// ---------------------------------------------------------------------------
// F0: fused  init(deg=1,count=0)  +  W-dup pack  +  dtype probe (block 0)
// ---------------------------------------------------------------------------
__global__ void k_f0(const void* __restrict__ ei, const float* __restrict__ W,
                     int n, int total_elems) {
    int i = blockIdx.x * blockDim.x + threadIdx.x;
    if (i < n) { g_deg[i] = 1.0f; g_count[i] = 0; }
    if (i < DIM * DIM) { float w = W[i]; g_Wdup[i] = pk2(w, w); }
    if (blockIdx.x == 0) {
        __shared__ int bad;
        if (threadIdx.x == 0) bad = 0;
        __syncthreads();
        const long long* p = (const long long*)ei;
        int cnt = total_elems < 2048 ? total_elems : 2048;
        for (int j = threadIdx.x; j < cnt; j += blockDim.x) {
            long long v = p[j];
            if (v < 0 || v >= (long long)n) bad = 1;
        }
        __syncthreads();
        if (threadIdx.x == 0) g_is64 = bad ? 0 : 1;
    }
}

// ---------------------------------------------------------------------------
// F1: fat kernel — blocks [0, gemm_blocks) run LN+GEMM; the rest run the single
// edge pass: weighted degree + ELL slot fill (src, weight). Independent phases.
// ---------------------------------------------------------------------------
__global__ __launch_bounds__(256) void k_f1(
    const float* __restrict__ x,
    const float* __restrict__ lnw, const float* __restrict__ lnb, int n,
    const void* __restrict__ ei, const float* __restrict__ ew, int E,
    int gemm_blocks)
{
    __shared__ float sX[64 * 132];
    const int tid  = threadIdx.x;

    if (blockIdx.x >= gemm_blocks) {
        // ---- edge pass: deg += w, slot = count[c]++, ell[slot] = (r, w) ----
        int e = (blockIdx.x - gemm_blocks) * 256 + tid;
        if (e < E) {
            int is64 = g_is64;
            int r = edge_idx(ei, is64, e);
            int c = edge_idx(ei, is64, (size_t)E + e);
            if ((unsigned)r < (unsigned)n && (unsigned)c < (unsigned)n) {
                float w = __ldg(ew + e);
                atomicAdd(&g_deg[c], w);
                int pos = atomicAdd(&g_count[c], 1);
                if (pos < ELLW)
                    g_ell[(size_t)c * ELLW + pos] = make_int2(r, __float_as_int(w));
            }
        }
        return;
    }

    // ---- LN + GEMM ----
    const int wid  = tid >> 5;
    const int lane = tid & 31;
    const int nb   = blockIdx.x * 64;

    float4 wv4 = *(const float4*)(lnw + lane * 4);
    float4 bv4 = *(const float4*)(lnb + lane * 4);
    #pragma unroll
    for (int i = 0; i < 8; i++) {
        int ln_node = wid * 8 + i;
        int gn = nb + ln_node;
        float4 v;
        if (gn < n) v = *(const float4*)(x + (size_t)gn * DIM + lane * 4);
        else        v = make_float4(0.f, 0.f, 0.f, 0.f);
        float s  = v.x + v.y + v.z + v.w;
        float sq = v.x * v.x + v.y * v.y + v.z * v.z + v.w * v.w;
        #pragma unroll
        for (int o = 16; o > 0; o >>= 1) {
            s  += __shfl_xor_sync(0xffffffffu, s, o);
            sq += __shfl_xor_sync(0xffffffffu, sq, o);
        }
        float mu  = s * (1.0f / DIM);
        float var = sq * (1.0f / DIM) - mu * mu;
        float rs  = rsqrtf(var + 1e-5f);
        float4 o4;
        o4.x = (v.x - mu) * rs * wv4.x + bv4.x;
        o4.y = (v.y - mu) * rs * wv4.y + bv4.y;
        o4.z = (v.z - mu) * rs * wv4.z + bv4.z;
        o4.w = (v.w - mu) * rs * wv4.w + bv4.w;
        *(float4*)(sX + ln_node * 132 + lane * 4) = o4;
    }
    __syncthreads();

    const int jb = wid * 16;
    unsigned long long accp[16];
    #pragma unroll
    for (int j = 0; j < 16; j++) accp[j] = 0ull;

    #pragma unroll 2
    for (int k = 0; k < DIM; k += 4) {
        float4 xa = *(const float4*)(sX + lane * 132 + k);
        float4 xb = *(const float4*)(sX + (lane + 32) * 132 + k);
        unsigned long long xp0 = pk2(xa.x, xb.x);
        unsigned long long xp1 = pk2(xa.y, xb.y);
        unsigned long long xp2 = pk2(xa.z, xb.z);
        unsigned long long xp3 = pk2(xa.w, xb.w);
        #pragma unroll
        for (int j = 0; j < 16; j++) {
            // pre-packed (w,w) pairs: no inner-loop mov.b64 packing
            const unsigned long long* Wd = g_Wdup + (size_t)(jb + j) * DIM + k;
            ulonglong2 w01 = *(const ulonglong2*)(Wd);       // warp-uniform
            ulonglong2 w23 = *(const ulonglong2*)(Wd + 2);
            ffma2(accp[j], xp0, w01.x);
            ffma2(accp[j], xp1, w01.y);
            ffma2(accp[j], xp2, w23.x);
            ffma2(accp[j], xp3, w23.y);
        }
    }

    int gn0 = nb + lane, gn1 = nb + lane + 32;
    float a0[16], a1[16];
    #pragma unroll
    for (int j = 0; j < 16; j++) { float2 f = upk2(accp[j]); a0[j] = f.x; a1[j] = f.y; }
    if (gn0 < n) {
        float* p = g_h + (size_t)gn0 * DIM + jb;
        #pragma unroll
        for (int q = 0; q < 4; q++)
            *(float4*)(p + q * 4) = make_float4(a0[q*4+0], a0[q*4+1], a0[q*4+2], a0[q*4+3]);
    }
    if (gn1 < n) {
        float* p = g_h + (size_t)gn1 * DIM + jb;
        #pragma unroll
        for (int q = 0; q < 4; q++)
            *(float4*)(p + q * 4) = make_float4(a1[q*4+0], a1[q*4+1], a1[q*4+2], a1[q*4+3]);
    }
}

// ---------------------------------------------------------------------------
// dinv = rsqrt(deg)
// ---------------------------------------------------------------------------
__global__ void k_dinv(int n) {
    int i = blockIdx.x * blockDim.x + threadIdx.x;
    if (i < n) {
        float d = g_deg[i];
        g_dinv[i] = d > 0.f ? rsqrtf(d) : 0.f;
    }
}

// ---------------------------------------------------------------------------
// Aggregate: TWO warps per node (even/odd ELL slots) -> 2x warp parallelism,
// half the serial chain. Partials merged via SMEM; warp-half 0 applies
// self-loop + bias + exact-erf GELU and stores.
// ---------------------------------------------------------------------------
__device__ __forceinline__ float gelu_e(float v) {
    return 0.5f * v * (1.0f + erff(v * 0.70710678118654752f));
}
__device__ __forceinline__ void fmaacc(float4& acc, float4 v, float s) {
    acc.x += v.x * s; acc.y += v.y * s; acc.z += v.z * s; acc.w += v.w * s;
}

__global__ __launch_bounds__(256) void k_aggregate(
    const float* __restrict__ bias, float* __restrict__ out, int n)
{
    __shared__ float4 sAcc[4][32];           // per-node partial from odd half
    int tid   = threadIdx.x;
    int wid   = tid >> 5;
    int lane  = tid & 31;
    int local = wid >> 1;                    // node slot within block (0..3)
    int half  = wid & 1;                     // 0 = even slots, 1 = odd slots
    int w     = blockIdx.x * 4 + local;
    bool active = (w < n);

    float4 acc = make_float4(0.f, 0.f, 0.f, 0.f);
    float dc = 0.f;
    if (active) {
        const float4* h4 = (const float4*)g_h;
        dc = g_dinv[w];
        if (half == 0) {                     // self-loop handled by even warp
            float sl = dc * dc;
            acc = __ldg(h4 + (size_t)w * 32 + lane);
            acc.x *= sl; acc.y *= sl; acc.z *= sl; acc.w *= sl;
        }
        int cnt = g_count[w]; if (cnt > ELLW) cnt = ELLW;
        const int2* ell = g_ell + (size_t)w * ELLW;
        int p = half;
        for (; p + 6 < cnt; p += 8) {        // 4 slots in flight (stride 2)
            int2 e0 = __ldg(ell + p);
            int2 e1 = __ldg(ell + p + 2);
            int2 e2 = __ldg(ell + p + 4);
            int2 e3 = __ldg(ell + p + 6);
            float4 v0 = __ldg(h4 + (size_t)e0.x * 32 + lane);
            float4 v1 = __ldg(h4 + (size_t)e1.x * 32 + lane);
            float4 v2 = __ldg(h4 + (size_t)e2.x * 32 + lane);
            float4 v3 = __ldg(h4 + (size_t)e3.x * 32 + lane);
            float n0 = __ldg(&g_dinv[e0.x]) * __int_as_float(e0.y) * dc;
            float n1 = __ldg(&g_dinv[e1.x]) * __int_as_float(e1.y) * dc;
            float n2 = __ldg(&g_dinv[e2.x]) * __int_as_float(e2.y) * dc;
            float n3 = __ldg(&g_dinv[e3.x]) * __int_as_float(e3.y) * dc;
            fmaacc(acc, v0, n0);
            fmaacc(acc, v1, n1);
            fmaacc(acc, v2, n2);
            fmaacc(acc, v3, n3);
        }
        for (; p < cnt; p += 2) {
            int2 e0 = __ldg(ell + p);
            float4 v0 = __ldg(h4 + (size_t)e0.x * 32 + lane);
            float n0 = __ldg(&g_dinv[e0.x]) * __int_as_float(e0.y) * dc;
            fmaacc(acc, v0, n0);
        }
    }

    if (half == 1) sAcc[local][lane] = acc;
    __syncthreads();

    if (half == 0 && active) {
        float4 o = sAcc[local][lane];
        acc.x += o.x; acc.y += o.y; acc.z += o.z; acc.w += o.w;
        float4 bb = ((const float4*)bias)[lane];
        acc.x = gelu_e(acc.x + bb.x);
        acc.y = gelu_e(acc.y + bb.y);
        acc.z = gelu_e(acc.z + bb.z);
        acc.w = gelu_e(acc.w + bb.w);
        ((float4*)out)[(size_t)w * 32 + lane] = acc;
    }
}

extern "C" void kernel_launch(void* const* d_in, const int* in_sizes, int n_in,
                              void* d_out, int out_size) {
    const float* x   = (const float*)d_in[0];
    const void*  ei  = d_in[1];
    const float* ew  = (const float*)d_in[2];
    const float* W   = (const float*)d_in[3];
    const float* b   = (const float*)d_in[4];
    const float* lnw = (const float*)d_in[5];
    const float* lnb = (const float*)d_in[6];
    float* out = (float*)d_out;

    int n  = in_sizes[0] / DIM;         // 50000
    int E  = in_sizes[2];               // 800000
    int nb = (n + 255) / 256;
    int gemm_blocks = (n + 63) / 64;
    int deg_blocks  = (E + 255) / 256;

    k_f0       <<<nb, 256>>>(ei, W, n, in_sizes[1]);
    k_f1       <<<gemm_blocks + deg_blocks, 256>>>(x, lnw, lnb, n, ei, ew, E, gemm_blocks);
    k_dinv     <<<nb, 256>>>(n);
    k_aggregate<<<(n + 3) / 4, 256>>>(b, out, n);
}

// round 14
// speedup vs baseline: 1.1730x; 1.1730x over previous
#include <cuda_runtime.h>
#include <math.h>

#define DIM 128
#define NMAX 50000
#define EMAX 800000
#define ELLW 96                             // max in-degree slots per node

// Scratch (no allocs allowed)
__device__ float g_h[(size_t)NMAX * DIM];   // h = LN(x) @ W^T
__device__ float g_deg[NMAX];
__device__ float g_dinv[NMAX];
__device__ int   g_count[NMAX];
__device__ int2  g_ell[(size_t)NMAX * ELLW]; // (src, ew-as-int) per ELL slot
__device__ int   g_is64;

__device__ __forceinline__ int edge_idx(const void* ei, int is64, size_t pos) {
    return is64 ? (int)((const long long*)ei)[pos] : ((const int*)ei)[pos];
}

// ---------------------------------------------------------------------------
// f32x2 packed-FMA helpers (FFMA2 is PTX-only on sm_103a)
// ---------------------------------------------------------------------------
__device__ __forceinline__ void ffma2(unsigned long long& acc,
                                      unsigned long long a, unsigned long long b) {
    asm("fma.rn.f32x2 %0, %1, %2, %0;" : "+l"(acc) : "l"(a), "l"(b));
}
__device__ __forceinline__ unsigned long long pk2(float lo, float hi) {
    unsigned long long r;
    asm("mov.b64 %0, {%1, %2};" : "=l"(r) : "f"(lo), "f"(hi));
    return r;
}
__device__ __forceinline__ float2 upk2(unsigned long long v) {
    float2 r;
    asm("mov.b64 {%0, %1}, %2;" : "=f"(r.x), "=f"(r.y) : "l"(v));
    return r;
}

// ---------------------------------------------------------------------------
// F0: fused  init(deg=1,count=0)  +  dtype probe (block 0)
// ---------------------------------------------------------------------------
__global__ void k_f0(const void* __restrict__ ei, int n, int total_elems) {
    int i = blockIdx.x * blockDim.x + threadIdx.x;
    if (i < n) { g_deg[i] = 1.0f; g_count[i] = 0; }
    if (blockIdx.x == 0) {
        __shared__ int bad;
        if (threadIdx.x == 0) bad = 0;
        __syncthreads();
        const long long* p = (const long long*)ei;
        int cnt = total_elems < 2048 ? total_elems : 2048;
        for (int j = threadIdx.x; j < cnt; j += blockDim.x) {
            long long v = p[j];
            if (v < 0 || v >= (long long)n) bad = 1;
        }
        __syncthreads();
        if (threadIdx.x == 0) g_is64 = bad ? 0 : 1;
    }
}

// ---------------------------------------------------------------------------
// F1: fat kernel — blocks [0, gemm_blocks) run LN+GEMM with a 128-node tile
// (halves the W LDG stream per FFMA2 vs 64-node tiles); remaining blocks run
// the single edge pass (deg += w, ELL slot fill). Independent phases overlap.
// ---------------------------------------------------------------------------
__global__ __launch_bounds__(256, 2) void k_f1(
    const float* __restrict__ x, const float* __restrict__ W,
    const float* __restrict__ lnw, const float* __restrict__ lnb, int n,
    const void* __restrict__ ei, const float* __restrict__ ew, int E,
    int gemm_blocks)
{
    extern __shared__ float sX[];           // 128 * 132 floats = 67.6 KB
    const int tid = threadIdx.x;

    if (blockIdx.x >= gemm_blocks) {
        // ---- edge pass ----
        int e = (blockIdx.x - gemm_blocks) * 256 + tid;
        if (e < E) {
            int is64 = g_is64;
            int r = edge_idx(ei, is64, e);
            int c = edge_idx(ei, is64, (size_t)E + e);
            if ((unsigned)r < (unsigned)n && (unsigned)c < (unsigned)n) {
                float w = __ldg(ew + e);
                atomicAdd(&g_deg[c], w);
                int pos = atomicAdd(&g_count[c], 1);
                if (pos < ELLW)
                    g_ell[(size_t)c * ELLW + pos] = make_int2(r, __float_as_int(w));
            }
        }
        return;
    }

    // ---- LN: warp wid normalizes nodes wid*16 .. wid*16+15 of this 128-tile ----
    const int wid  = tid >> 5;
    const int lane = tid & 31;
    const int nb   = blockIdx.x * 128;

    float4 wv4 = *(const float4*)(lnw + lane * 4);
    float4 bv4 = *(const float4*)(lnb + lane * 4);
    #pragma unroll
    for (int i = 0; i < 16; i++) {
        int ln_node = wid * 16 + i;
        int gn = nb + ln_node;
        float4 v;
        if (gn < n) v = *(const float4*)(x + (size_t)gn * DIM + lane * 4);
        else        v = make_float4(0.f, 0.f, 0.f, 0.f);
        float s  = v.x + v.y + v.z + v.w;
        float sq = v.x * v.x + v.y * v.y + v.z * v.z + v.w * v.w;
        #pragma unroll
        for (int o = 16; o > 0; o >>= 1) {
            s  += __shfl_xor_sync(0xffffffffu, s, o);
            sq += __shfl_xor_sync(0xffffffffu, sq, o);
        }
        float mu  = s * (1.0f / DIM);
        float var = sq * (1.0f / DIM) - mu * mu;
        float rs  = rsqrtf(var + 1e-5f);
        float4 o4;
        o4.x = (v.x - mu) * rs * wv4.x + bv4.x;
        o4.y = (v.y - mu) * rs * wv4.y + bv4.y;
        o4.z = (v.z - mu) * rs * wv4.z + bv4.z;
        o4.w = (v.w - mu) * rs * wv4.w + bv4.w;
        *(float4*)(sX + ln_node * 132 + lane * 4) = o4;
    }
    __syncthreads();

    // ---- GEMM: warp owns cols [16w,16w+16); lane owns node pairs
    //      A=(lane, lane+32), B=(lane+64, lane+96) as f32x2 accumulators ----
    const int jb = wid * 16;
    unsigned long long accA[16], accB[16];
    #pragma unroll
    for (int j = 0; j < 16; j++) { accA[j] = 0ull; accB[j] = 0ull; }

    #pragma unroll 2
    for (int k = 0; k < DIM; k += 4) {
        float4 xa = *(const float4*)(sX + lane * 132 + k);
        float4 xb = *(const float4*)(sX + (lane + 32) * 132 + k);
        float4 xc = *(const float4*)(sX + (lane + 64) * 132 + k);
        float4 xd = *(const float4*)(sX + (lane + 96) * 132 + k);
        unsigned long long pA0 = pk2(xa.x, xb.x), pA1 = pk2(xa.y, xb.y);
        unsigned long long pA2 = pk2(xa.z, xb.z), pA3 = pk2(xa.w, xb.w);
        unsigned long long pB0 = pk2(xc.x, xd.x), pB1 = pk2(xc.y, xd.y);
        unsigned long long pB2 = pk2(xc.z, xd.z), pB3 = pk2(xc.w, xd.w);
        #pragma unroll
        for (int j = 0; j < 16; j++) {
            float4 w = *(const float4*)(W + (size_t)(jb + j) * DIM + k);  // warp-uniform, L1-resident
            unsigned long long w0 = pk2(w.x, w.x), w1 = pk2(w.y, w.y);
            unsigned long long w2 = pk2(w.z, w.z), w3 = pk2(w.w, w.w);
            ffma2(accA[j], pA0, w0); ffma2(accB[j], pB0, w0);
            ffma2(accA[j], pA1, w1); ffma2(accB[j], pB1, w1);
            ffma2(accA[j], pA2, w2); ffma2(accB[j], pB2, w2);
            ffma2(accA[j], pA3, w3); ffma2(accB[j], pB3, w3);
        }
    }

    // ---- store 4 rows ----
    #pragma unroll
    for (int half = 0; half < 2; half++) {
        unsigned long long* acc = half ? accB : accA;
        int r0 = nb + lane + half * 64;
        int r1 = r0 + 32;
        float a0[16], a1[16];
        #pragma unroll
        for (int j = 0; j < 16; j++) { float2 f = upk2(acc[j]); a0[j] = f.x; a1[j] = f.y; }
        if (r0 < n) {
            float* p = g_h + (size_t)r0 * DIM + jb;
            #pragma unroll
            for (int q = 0; q < 4; q++)
                *(float4*)(p + q * 4) = make_float4(a0[q*4+0], a0[q*4+1], a0[q*4+2], a0[q*4+3]);
        }
        if (r1 < n) {
            float* p = g_h + (size_t)r1 * DIM + jb;
            #pragma unroll
            for (int q = 0; q < 4; q++)
                *(float4*)(p + q * 4) = make_float4(a1[q*4+0], a1[q*4+1], a1[q*4+2], a1[q*4+3]);
        }
    }
}

// ---------------------------------------------------------------------------
// dinv = rsqrt(deg)
// ---------------------------------------------------------------------------
__global__ void k_dinv(int n) {
    int i = blockIdx.x * blockDim.x + threadIdx.x;
    if (i < n) {
        float d = g_deg[i];
        g_dinv[i] = d > 0.f ? rsqrtf(d) : 0.f;
    }
}

// ---------------------------------------------------------------------------
// Aggregate: one warp per node (round-10 structure, which measured equal to
// the 2-warp split), with f32x2 accumulation to halve fma-pipe issue.
// ---------------------------------------------------------------------------
__device__ __forceinline__ float gelu_e(float v) {
    return 0.5f * v * (1.0f + erff(v * 0.70710678118654752f));
}

__global__ __launch_bounds__(256) void k_aggregate(
    const float* __restrict__ bias, float* __restrict__ out, int n)
{
    int w    = (blockIdx.x * 256 + threadIdx.x) >> 5;
    int lane = threadIdx.x & 31;
    if (w >= n) return;

    const ulonglong2* h2 = (const ulonglong2*)g_h;   // row = 32 ulonglong2
    float dc = g_dinv[w];
    float sl = dc * dc;                              // self-loop: 1/deg
    unsigned long long accA = 0ull, accB = 0ull;
    {
        ulonglong2 v = __ldg(h2 + (size_t)w * 32 + lane);
        unsigned long long s2 = pk2(sl, sl);
        ffma2(accA, v.x, s2);
        ffma2(accB, v.y, s2);
    }

    int cnt = g_count[w]; if (cnt > ELLW) cnt = ELLW;
    const int2* ell = g_ell + (size_t)w * ELLW;
    int p = 0;
    for (; p + 4 <= cnt; p += 4) {                   // MLP = 4 gathers
        int2 e0 = __ldg(ell + p);
        int2 e1 = __ldg(ell + p + 1);
        int2 e2 = __ldg(ell + p + 2);
        int2 e3 = __ldg(ell + p + 3);
        ulonglong2 v0 = __ldg(h2 + (size_t)e0.x * 32 + lane);
        ulonglong2 v1 = __ldg(h2 + (size_t)e1.x * 32 + lane);
        ulonglong2 v2 = __ldg(h2 + (size_t)e2.x * 32 + lane);
        ulonglong2 v3 = __ldg(h2 + (size_t)e3.x * 32 + lane);
        float n0 = __ldg(&g_dinv[e0.x]) * __int_as_float(e0.y) * dc;
        float n1 = __ldg(&g_dinv[e1.x]) * __int_as_float(e1.y) * dc;
        float n2 = __ldg(&g_dinv[e2.x]) * __int_as_float(e2.y) * dc;
        float n3 = __ldg(&g_dinv[e3.x]) * __int_as_float(e3.y) * dc;
        unsigned long long m0 = pk2(n0, n0), m1 = pk2(n1, n1);
        unsigned long long m2 = pk2(n2, n2), m3 = pk2(n3, n3);
        ffma2(accA, v0.x, m0); ffma2(accB, v0.y, m0);
        ffma2(accA, v1.x, m1); ffma2(accB, v1.y, m1);
        ffma2(accA, v2.x, m2); ffma2(accB, v2.y, m2);
        ffma2(accA, v3.x, m3); ffma2(accB, v3.y, m3);
    }
    for (; p < cnt; p++) {
        int2 e0 = __ldg(ell + p);
        ulonglong2 v0 = __ldg(h2 + (size_t)e0.x * 32 + lane);
        float n0 = __ldg(&g_dinv[e0.x]) * __int_as_float(e0.y) * dc;
        unsigned long long m0 = pk2(n0, n0);
        ffma2(accA, v0.x, m0); ffma2(accB, v0.y, m0);
    }

    float2 fA = upk2(accA), fB = upk2(accB);
    float4 bb = ((const float4*)bias)[lane];
    float4 o;
    o.x = gelu_e(fA.x + bb.x);
    o.y = gelu_e(fA.y + bb.y);
    o.z = gelu_e(fB.x + bb.z);
    o.w = gelu_e(fB.y + bb.w);
    ((float4*)out)[(size_t)w * 32 + lane] = o;
}

extern "C" void kernel_launch(void* const* d_in, const int* in_sizes, int n_in,
                              void* d_out, int out_size) {
    const float* x   = (const float*)d_in[0];
    const void*  ei  = d_in[1];
    const float* ew  = (const float*)d_in[2];
    const float* W   = (const float*)d_in[3];
    const float* b   = (const float*)d_in[4];
    const float* lnw = (const float*)d_in[5];
    const float* lnb = (const float*)d_in[6];
    float* out = (float*)d_out;

    int n  = in_sizes[0] / DIM;         // 50000
    int E  = in_sizes[2];               // 800000
    int nb = (n + 255) / 256;
    int gemm_blocks = (n + 127) / 128;
    int deg_blocks  = (E + 255) / 256;
    int smem = 128 * 132 * sizeof(float);   // 67,584 B dynamic

    static int attr_done = 0;
    if (!attr_done) {
        cudaFuncSetAttribute(k_f1, cudaFuncAttributeMaxDynamicSharedMemorySize, smem);
        attr_done = 1;
    }

    k_f0       <<<nb, 256>>>(ei, n, in_sizes[1]);
    k_f1       <<<gemm_blocks + deg_blocks, 256, smem>>>(x, W, lnw, lnb, n, ei, ew, E, gemm_blocks);
    k_dinv     <<<nb, 256>>>(n);
    k_aggregate<<<(n * 32 + 255) / 256, 256>>>(b, out, n);
}

// round 16
// speedup vs baseline: 1.3476x; 1.1488x over previous
#include <cuda_runtime.h>
#include <math.h>

#define DIM 128
#define NMAX 50000
#define EMAX 800000
#define ELLW 96                             // max in-degree slots per node

// Scratch (no allocs allowed)
__device__ float g_h[(size_t)NMAX * DIM];   // h = LN(x) @ W^T
__device__ float g_deg[NMAX];
__device__ float g_dinv[NMAX];
__device__ int   g_count[NMAX];
__device__ int2  g_ell[(size_t)NMAX * ELLW]; // (src, ew-as-int) per ELL slot
__device__ unsigned long long g_Wpair[(DIM / 2) * DIM]; // (W[2p][k], W[2p+1][k]) pairs, 64KB
__device__ int   g_is64;

__device__ __forceinline__ int edge_idx(const void* ei, int is64, size_t pos) {
    return is64 ? (int)((const long long*)ei)[pos] : ((const int*)ei)[pos];
}

// ---------------------------------------------------------------------------
// f32x2 packed-FMA helpers (FFMA2 is PTX-only on sm_103a)
// ---------------------------------------------------------------------------
__device__ __forceinline__ void ffma2(unsigned long long& acc,
                                      unsigned long long a, unsigned long long b) {
    asm("fma.rn.f32x2 %0, %1, %2, %0;" : "+l"(acc) : "l"(a), "l"(b));
}
__device__ __forceinline__ unsigned long long pk2(float lo, float hi) {
    unsigned long long r;
    asm("mov.b64 %0, {%1, %2};" : "=l"(r) : "f"(lo), "f"(hi));
    return r;
}
__device__ __forceinline__ float2 upk2(unsigned long long v) {
    float2 r;
    asm("mov.b64 {%0, %1}, %2;" : "=f"(r.x), "=f"(r.y) : "l"(v));
    return r;
}

// ---------------------------------------------------------------------------
// F0: fused  init(deg=1,count=0)  +  Wpair pack  +  dtype probe (block 0)
// Wpair keeps W's exact 64KB footprint (no duplication — round-11 lesson).
// ---------------------------------------------------------------------------
__global__ void k_f0(const void* __restrict__ ei, const float* __restrict__ W,
                     int n, int total_elems) {
    int i = blockIdx.x * blockDim.x + threadIdx.x;
    if (i < n) { g_deg[i] = 1.0f; g_count[i] = 0; }
    if (i < (DIM / 2) * DIM) {
        int pr = i >> 7;          // pair row (0..63)
        int k  = i & (DIM - 1);
        g_Wpair[i] = pk2(W[(size_t)(2 * pr) * DIM + k], W[(size_t)(2 * pr + 1) * DIM + k]);
    }
    if (blockIdx.x == 0) {
        __shared__ int bad;
        if (threadIdx.x == 0) bad = 0;
        __syncthreads();
        const long long* p = (const long long*)ei;
        int cnt = total_elems < 2048 ? total_elems : 2048;
        for (int j = threadIdx.x; j < cnt; j += blockDim.x) {
            long long v = p[j];
            if (v < 0 || v >= (long long)n) bad = 1;
        }
        __syncthreads();
        if (threadIdx.x == 0) g_is64 = bad ? 0 : 1;
    }
}

// ---------------------------------------------------------------------------
// F1: fat kernel — blocks [0, gemm_blocks) run LN+GEMM (64-node tile, j-pair
// f32x2 inner loop, zero W-pack movs); remaining blocks run the edge pass.
// 33.8KB static SMEM keeps 6 CTAs/SM so the edge half stays well-occupied.
// ---------------------------------------------------------------------------
__global__ __launch_bounds__(256) void k_f1(
    const float* __restrict__ x,
    const float* __restrict__ lnw, const float* __restrict__ lnb, int n,
    const void* __restrict__ ei, const float* __restrict__ ew, int E,
    int gemm_blocks)
{
    __shared__ float sX[64 * 132];
    const int tid = threadIdx.x;

    if (blockIdx.x >= gemm_blocks) {
        // ---- edge pass: deg += w, slot = count[c]++, ell[slot] = (r, w) ----
        int e = (blockIdx.x - gemm_blocks) * 256 + tid;
        if (e < E) {
            int is64 = g_is64;
            int r = edge_idx(ei, is64, e);
            int c = edge_idx(ei, is64, (size_t)E + e);
            if ((unsigned)r < (unsigned)n && (unsigned)c < (unsigned)n) {
                float w = __ldg(ew + e);
                atomicAdd(&g_deg[c], w);
                int pos = atomicAdd(&g_count[c], 1);
                if (pos < ELLW)
                    g_ell[(size_t)c * ELLW + pos] = make_int2(r, __float_as_int(w));
            }
        }
        return;
    }

    // ---- LN: warp wid normalizes nodes wid*8 .. wid*8+7 ----
    const int wid  = tid >> 5;
    const int lane = tid & 31;
    const int nb   = blockIdx.x * 64;

    float4 wv4 = *(const float4*)(lnw + lane * 4);
    float4 bv4 = *(const float4*)(lnb + lane * 4);
    #pragma unroll
    for (int i = 0; i < 8; i++) {
        int ln_node = wid * 8 + i;
        int gn = nb + ln_node;
        float4 v;
        if (gn < n) v = *(const float4*)(x + (size_t)gn * DIM + lane * 4);
        else        v = make_float4(0.f, 0.f, 0.f, 0.f);
        float s  = v.x + v.y + v.z + v.w;
        float sq = v.x * v.x + v.y * v.y + v.z * v.z + v.w * v.w;
        #pragma unroll
        for (int o = 16; o > 0; o >>= 1) {
            s  += __shfl_xor_sync(0xffffffffu, s, o);
            sq += __shfl_xor_sync(0xffffffffu, sq, o);
        }
        float mu  = s * (1.0f / DIM);
        float var = sq * (1.0f / DIM) - mu * mu;
        float rs  = rsqrtf(var + 1e-5f);
        float4 o4;
        o4.x = (v.x - mu) * rs * wv4.x + bv4.x;
        o4.y = (v.y - mu) * rs * wv4.y + bv4.y;
        o4.z = (v.z - mu) * rs * wv4.z + bv4.z;
        o4.w = (v.w - mu) * rs * wv4.w + bv4.w;
        *(float4*)(sX + ln_node * 132 + lane * 4) = o4;
    }
    __syncthreads();

    // ---- GEMM: warp owns j-pairs [8w, 8w+8) = cols [16w, 16w+16);
    //      lane owns nodes A=lane, B=lane+32.
    //      accA[p] = (h[A][2p], h[A][2p+1]) as f32x2 — no W packing movs. ----
    const int pb = wid * 8;                  // pair base
    unsigned long long accA[8], accB[8];
    #pragma unroll
    for (int p = 0; p < 8; p++) { accA[p] = 0ull; accB[p] = 0ull; }

    #pragma unroll 2
    for (int k = 0; k < DIM; k += 4) {
        float4 xa = *(const float4*)(sX + lane * 132 + k);
        float4 xb = *(const float4*)(sX + (lane + 32) * 132 + k);
        unsigned long long a0 = pk2(xa.x, xa.x), a1 = pk2(xa.y, xa.y);
        unsigned long long a2 = pk2(xa.z, xa.z), a3 = pk2(xa.w, xa.w);
        unsigned long long b0 = pk2(xb.x, xb.x), b1 = pk2(xb.y, xb.y);
        unsigned long long b2 = pk2(xb.z, xb.z), b3 = pk2(xb.w, xb.w);
        #pragma unroll
        for (int p = 0; p < 8; p++) {
            const unsigned long long* Wp = g_Wpair + (size_t)(pb + p) * DIM + k;  // warp-uniform
            ulonglong2 w01 = *(const ulonglong2*)(Wp);
            ulonglong2 w23 = *(const ulonglong2*)(Wp + 2);
            ffma2(accA[p], a0, w01.x); ffma2(accB[p], b0, w01.x);
            ffma2(accA[p], a1, w01.y); ffma2(accB[p], b1, w01.y);
            ffma2(accA[p], a2, w23.x); ffma2(accB[p], b2, w23.x);
            ffma2(accA[p], a3, w23.y); ffma2(accB[p], b3, w23.y);
        }
    }

    // ---- store: accA[p] gives consecutive cols (2p, 2p+1) ----
    int gn0 = nb + lane, gn1 = nb + lane + 32;
    float a0f[16], a1f[16];
    #pragma unroll
    for (int p = 0; p < 8; p++) {
        float2 fA = upk2(accA[p]); a0f[2*p] = fA.x; a0f[2*p+1] = fA.y;
        float2 fB = upk2(accB[p]); a1f[2*p] = fB.x; a1f[2*p+1] = fB.y;
    }
    if (gn0 < n) {
        float* p = g_h + (size_t)gn0 * DIM + wid * 16;
        #pragma unroll
        for (int q = 0; q < 4; q++)
            *(float4*)(p + q * 4) = make_float4(a0f[q*4+0], a0f[q*4+1], a0f[q*4+2], a0f[q*4+3]);
    }
    if (gn1 < n) {
        float* p = g_h + (size_t)gn1 * DIM + wid * 16;
        #pragma unroll
        for (int q = 0; q < 4; q++)
            *(float4*)(p + q * 4) = make_float4(a1f[q*4+0], a1f[q*4+1], a1f[q*4+2], a1f[q*4+3]);
    }
}

// ---------------------------------------------------------------------------
// dinv = rsqrt(deg)
// ---------------------------------------------------------------------------
__global__ void k_dinv(int n) {
    int i = blockIdx.x * blockDim.x + threadIdx.x;
    if (i < n) {
        float d = g_deg[i];
        g_dinv[i] = d > 0.f ? rsqrtf(d) : 0.f;
    }
}

// ---------------------------------------------------------------------------
// Aggregate: one warp per node, f32x2 accumulation (round-14 form, measured
// equal-best 46.6µs — at its L2-gather floor).
// ---------------------------------------------------------------------------
__device__ __forceinline__ float gelu_e(float v) {
    return 0.5f * v * (1.0f + erff(v * 0.70710678118654752f));
}

__global__ __launch_bounds__(256) void k_aggregate(
    const float* __restrict__ bias, float* __restrict__ out, int n)
{
    int w    = (blockIdx.x * 256 + threadIdx.x) >> 5;
    int lane = threadIdx.x & 31;
    if (w >= n) return;

    const ulonglong2* h2 = (const ulonglong2*)g_h;   // row = 32 ulonglong2
    float dc = g_dinv[w];
    float sl = dc * dc;                              // self-loop: 1/deg
    unsigned long long accA = 0ull, accB = 0ull;
    {
        ulonglong2 v = __ldg(h2 + (size_t)w * 32 + lane);
        unsigned long long s2 = pk2(sl, sl);
        ffma2(accA, v.x, s2);
        ffma2(accB, v.y, s2);
    }

    int cnt = g_count[w]; if (cnt > ELLW) cnt = ELLW;
    const int2* ell = g_ell + (size_t)w * ELLW;
    int p = 0;
    for (; p + 4 <= cnt; p += 4) {                   // MLP = 4 gathers
        int2 e0 = __ldg(ell + p);
        int2 e1 = __ldg(ell + p + 1);
        int2 e2 = __ldg(ell + p + 2);
        int2 e3 = __ldg(ell + p + 3);
        ulonglong2 v0 = __ldg(h2 + (size_t)e0.x * 32 + lane);
        ulonglong2 v1 = __ldg(h2 + (size_t)e1.x * 32 + lane);
        ulonglong2 v2 = __ldg(h2 + (size_t)e2.x * 32 + lane);
        ulonglong2 v3 = __ldg(h2 + (size_t)e3.x * 32 + lane);
        float n0 = __ldg(&g_dinv[e0.x]) * __int_as_float(e0.y) * dc;
        float n1 = __ldg(&g_dinv[e1.x]) * __int_as_float(e1.y) * dc;
        float n2 = __ldg(&g_dinv[e2.x]) * __int_as_float(e2.y) * dc;
        float n3 = __ldg(&g_dinv[e3.x]) * __int_as_float(e3.y) * dc;
        unsigned long long m0 = pk2(n0, n0), m1 = pk2(n1, n1);
        unsigned long long m2 = pk2(n2, n2), m3 = pk2(n3, n3);
        ffma2(accA, v0.x, m0); ffma2(accB, v0.y, m0);
        ffma2(accA, v1.x, m1); ffma2(accB, v1.y, m1);
        ffma2(accA, v2.x, m2); ffma2(accB, v2.y, m2);
        ffma2(accA, v3.x, m3); ffma2(accB, v3.y, m3);
    }
    for (; p < cnt; p++) {
        int2 e0 = __ldg(ell + p);
        ulonglong2 v0 = __ldg(h2 + (size_t)e0.x * 32 + lane);
        float n0 = __ldg(&g_dinv[e0.x]) * __int_as_float(e0.y) * dc;
        unsigned long long m0 = pk2(n0, n0);
        ffma2(accA, v0.x, m0); ffma2(accB, v0.y, m0);
    }

    float2 fA = upk2(accA), fB = upk2(accB);
    float4 bb = ((const float4*)bias)[lane];
    float4 o;
    o.x = gelu_e(fA.x + bb.x);
    o.y = gelu_e(fA.y + bb.y);
    o.z = gelu_e(fB.x + bb.z);
    o.w = gelu_e(fB.y + bb.w);
    ((float4*)out)[(size_t)w * 32 + lane] = o;
}

extern "C" void kernel_launch(void* const* d_in, const int* in_sizes, int n_in,
                              void* d_out, int out_size) {
    const float* x   = (const float*)d_in[0];
    const void*  ei  = d_in[1];
    const float* ew  = (const float*)d_in[2];
    const float* W   = (const float*)d_in[3];
    const float* b   = (const float*)d_in[4];
    const float* lnw = (const float*)d_in[5];
    const float* lnb = (const float*)d_in[6];
    float* out = (float*)d_out;

    int n  = in_sizes[0] / DIM;         // 50000
    int E  = in_sizes[2];               // 800000
    int nb = (n + 255) / 256;
    int gemm_blocks = (n + 63) / 64;
    int deg_blocks  = (E + 255) / 256;

    k_f0       <<<nb, 256>>>(ei, W, n, in_sizes[1]);
    k_f1       <<<gemm_blocks + deg_blocks, 256>>>(x, lnw, lnb, n, ei, ew, E, gemm_blocks);
    k_dinv     <<<nb, 256>>>(n);
    k_aggregate<<<(n * 32 + 255) / 256, 256>>>(b, out, n);
}

// round 17
// speedup vs baseline: 1.4436x; 1.0713x over previous
#include <cuda_runtime.h>
#include <math.h>

#define DIM 128
#define NMAX 50000
#define EMAX 800000
#define ELLW 96                             // max in-degree slots per node

// Scratch (no allocs allowed)
__device__ float g_h[(size_t)NMAX * DIM];   // h = LN(x) @ W^T
__device__ float g_deg[NMAX];
__device__ int   g_count[NMAX];
__device__ int2  g_ell[(size_t)NMAX * ELLW]; // (src, ew-as-int) per CSR slot
__device__ unsigned long long g_Wpair[(DIM / 2) * DIM]; // (W[2p][k], W[2p+1][k]) pairs, 64KB
__device__ int   g_is64;

__device__ __forceinline__ int edge_idx(const void* ei, int is64, size_t pos) {
    return is64 ? (int)((const long long*)ei)[pos] : ((const int*)ei)[pos];
}

// ---------------------------------------------------------------------------
// f32x2 packed-FMA helpers (FFMA2 is PTX-only on sm_103a)
// ---------------------------------------------------------------------------
__device__ __forceinline__ void ffma2(unsigned long long& acc,
                                      unsigned long long a, unsigned long long b) {
    asm("fma.rn.f32x2 %0, %1, %2, %0;" : "+l"(acc) : "l"(a), "l"(b));
}
__device__ __forceinline__ unsigned long long pk2(float lo, float hi) {
    unsigned long long r;
    asm("mov.b64 %0, {%1, %2};" : "=l"(r) : "f"(lo), "f"(hi));
    return r;
}
__device__ __forceinline__ float2 upk2(unsigned long long v) {
    float2 r;
    asm("mov.b64 {%0, %1}, %2;" : "=f"(r.x), "=f"(r.y) : "l"(v));
    return r;
}

// ---------------------------------------------------------------------------
// F0: fused  init(deg=1,count=0)  +  Wpair pack  +  dtype probe (block 0)
// ---------------------------------------------------------------------------
__global__ void k_f0(const void* __restrict__ ei, const float* __restrict__ W,
                     int n, int total_elems) {
    int i = blockIdx.x * blockDim.x + threadIdx.x;
    if (i < n) { g_deg[i] = 1.0f; g_count[i] = 0; }
    if (i < (DIM / 2) * DIM) {
        int pr = i >> 7;          // pair row (0..63)
        int k  = i & (DIM - 1);
        g_Wpair[i] = pk2(W[(size_t)(2 * pr) * DIM + k], W[(size_t)(2 * pr + 1) * DIM + k]);
    }
    if (blockIdx.x == 0) {
        __shared__ int bad;
        if (threadIdx.x == 0) bad = 0;
        __syncthreads();
        const long long* p = (const long long*)ei;
        int cnt = total_elems < 2048 ? total_elems : 2048;
        for (int j = threadIdx.x; j < cnt; j += blockDim.x) {
            long long v = p[j];
            if (v < 0 || v >= (long long)n) bad = 1;
        }
        __syncthreads();
        if (threadIdx.x == 0) g_is64 = bad ? 0 : 1;
    }
}

// ---------------------------------------------------------------------------
// F1: fat kernel — blocks [0, gemm_blocks) run LN+GEMM (64-node tile, j-pair
// f32x2 inner loop, zero W-pack movs); remaining blocks run the edge pass.
// (unchanged from the 123.6µs round-16 winner)
// ---------------------------------------------------------------------------
__global__ __launch_bounds__(256) void k_f1(
    const float* __restrict__ x,
    const float* __restrict__ lnw, const float* __restrict__ lnb, int n,
    const void* __restrict__ ei, const float* __restrict__ ew, int E,
    int gemm_blocks)
{
    __shared__ float sX[64 * 132];
    const int tid = threadIdx.x;

    if (blockIdx.x >= gemm_blocks) {
        // ---- edge pass: deg += w, slot = count[c]++, ell[slot] = (r, w) ----
        int e = (blockIdx.x - gemm_blocks) * 256 + tid;
        if (e < E) {
            int is64 = g_is64;
            int r = edge_idx(ei, is64, e);
            int c = edge_idx(ei, is64, (size_t)E + e);
            if ((unsigned)r < (unsigned)n && (unsigned)c < (unsigned)n) {
                float w = __ldg(ew + e);
                atomicAdd(&g_deg[c], w);
                int pos = atomicAdd(&g_count[c], 1);
                if (pos < ELLW)
                    g_ell[(size_t)c * ELLW + pos] = make_int2(r, __float_as_int(w));
            }
        }
        return;
    }

    // ---- LN: warp wid normalizes nodes wid*8 .. wid*8+7 ----
    const int wid  = tid >> 5;
    const int lane = tid & 31;
    const int nb   = blockIdx.x * 64;

    float4 wv4 = *(const float4*)(lnw + lane * 4);
    float4 bv4 = *(const float4*)(lnb + lane * 4);
    #pragma unroll
    for (int i = 0; i < 8; i++) {
        int ln_node = wid * 8 + i;
        int gn = nb + ln_node;
        float4 v;
        if (gn < n) v = *(const float4*)(x + (size_t)gn * DIM + lane * 4);
        else        v = make_float4(0.f, 0.f, 0.f, 0.f);
        float s  = v.x + v.y + v.z + v.w;
        float sq = v.x * v.x + v.y * v.y + v.z * v.z + v.w * v.w;
        #pragma unroll
        for (int o = 16; o > 0; o >>= 1) {
            s  += __shfl_xor_sync(0xffffffffu, s, o);
            sq += __shfl_xor_sync(0xffffffffu, sq, o);
        }
        float mu  = s * (1.0f / DIM);
        float var = sq * (1.0f / DIM) - mu * mu;
        float rs  = rsqrtf(var + 1e-5f);
        float4 o4;
        o4.x = (v.x - mu) * rs * wv4.x + bv4.x;
        o4.y = (v.y - mu) * rs * wv4.y + bv4.y;
        o4.z = (v.z - mu) * rs * wv4.z + bv4.z;
        o4.w = (v.w - mu) * rs * wv4.w + bv4.w;
        *(float4*)(sX + ln_node * 132 + lane * 4) = o4;
    }
    __syncthreads();

    // ---- GEMM: warp owns j-pairs [8w, 8w+8); lane owns nodes A=lane, B=lane+32 ----
    const int pb = wid * 8;
    unsigned long long accA[8], accB[8];
    #pragma unroll
    for (int p = 0; p < 8; p++) { accA[p] = 0ull; accB[p] = 0ull; }

    #pragma unroll 2
    for (int k = 0; k < DIM; k += 4) {
        float4 xa = *(const float4*)(sX + lane * 132 + k);
        float4 xb = *(const float4*)(sX + (lane + 32) * 132 + k);
        unsigned long long a0 = pk2(xa.x, xa.x), a1 = pk2(xa.y, xa.y);
        unsigned long long a2 = pk2(xa.z, xa.z), a3 = pk2(xa.w, xa.w);
        unsigned long long b0 = pk2(xb.x, xb.x), b1 = pk2(xb.y, xb.y);
        unsigned long long b2 = pk2(xb.z, xb.z), b3 = pk2(xb.w, xb.w);
        #pragma unroll
        for (int p = 0; p < 8; p++) {
            const unsigned long long* Wp = g_Wpair + (size_t)(pb + p) * DIM + k;  // warp-uniform
            ulonglong2 w01 = *(const ulonglong2*)(Wp);
            ulonglong2 w23 = *(const ulonglong2*)(Wp + 2);
            ffma2(accA[p], a0, w01.x); ffma2(accB[p], b0, w01.x);
            ffma2(accA[p], a1, w01.y); ffma2(accB[p], b1, w01.y);
            ffma2(accA[p], a2, w23.x); ffma2(accB[p], b2, w23.x);
            ffma2(accA[p], a3, w23.y); ffma2(accB[p], b3, w23.y);
        }
    }

    int gn0 = nb + lane, gn1 = nb + lane + 32;
    float a0f[16], a1f[16];
    #pragma unroll
    for (int p = 0; p < 8; p++) {
        float2 fA = upk2(accA[p]); a0f[2*p] = fA.x; a0f[2*p+1] = fA.y;
        float2 fB = upk2(accB[p]); a1f[2*p] = fB.x; a1f[2*p+1] = fB.y;
    }
    if (gn0 < n) {
        float* p = g_h + (size_t)gn0 * DIM + wid * 16;
        #pragma unroll
        for (int q = 0; q < 4; q++)
            *(float4*)(p + q * 4) = make_float4(a0f[q*4+0], a0f[q*4+1], a0f[q*4+2], a0f[q*4+3]);
    }
    if (gn1 < n) {
        float* p = g_h + (size_t)gn1 * DIM + wid * 16;
        #pragma unroll
        for (int q = 0; q < 4; q++)
            *(float4*)(p + q * 4) = make_float4(a1f[q*4+0], a1f[q*4+1], a1f[q*4+2], a1f[q*4+3]);
    }
}

// ---------------------------------------------------------------------------
// Aggregate: one warp per node; unroll-8 with int4 ELL loads (MLP=8);
// dinv computed inline from deg (k_dinv kernel eliminated);
// fused self-loop + bias + exact-erf GELU.
// ---------------------------------------------------------------------------
__device__ __forceinline__ float gelu_e(float v) {
    return 0.5f * v * (1.0f + erff(v * 0.70710678118654752f));
}

__global__ __launch_bounds__(256) void k_aggregate(
    const float* __restrict__ bias, float* __restrict__ out, int n)
{
    int w    = (blockIdx.x * 256 + threadIdx.x) >> 5;
    int lane = threadIdx.x & 31;
    if (w >= n) return;

    const ulonglong2* h2 = (const ulonglong2*)g_h;   // row = 32 ulonglong2
    float dc = rsqrtf(g_deg[w]);                     // deg >= 1 always (self-loop)
    float sl = dc * dc;                              // self-loop: 1/deg
    unsigned long long accA = 0ull, accB = 0ull;
    {
        ulonglong2 v = __ldg(h2 + (size_t)w * 32 + lane);
        unsigned long long s2 = pk2(sl, sl);
        ffma2(accA, v.x, s2);
        ffma2(accB, v.y, s2);
    }

    int cnt = g_count[w]; if (cnt > ELLW) cnt = ELLW;
    const int2* ell = g_ell + (size_t)w * ELLW;      // 768B-aligned -> int4 ok
    int p = 0;
    for (; p + 8 <= cnt; p += 8) {                   // MLP = 8 gathers in flight
        int4 q0 = __ldg((const int4*)(ell + p));     // edges (x,y),(z,w)
        int4 q1 = __ldg((const int4*)(ell + p + 2));
        int4 q2 = __ldg((const int4*)(ell + p + 4));
        int4 q3 = __ldg((const int4*)(ell + p + 6));
        ulonglong2 v0 = __ldg(h2 + (size_t)q0.x * 32 + lane);
        ulonglong2 v1 = __ldg(h2 + (size_t)q0.z * 32 + lane);
        ulonglong2 v2 = __ldg(h2 + (size_t)q1.x * 32 + lane);
        ulonglong2 v3 = __ldg(h2 + (size_t)q1.z * 32 + lane);
        ulonglong2 v4 = __ldg(h2 + (size_t)q2.x * 32 + lane);
        ulonglong2 v5 = __ldg(h2 + (size_t)q2.z * 32 + lane);
        ulonglong2 v6 = __ldg(h2 + (size_t)q3.x * 32 + lane);
        ulonglong2 v7 = __ldg(h2 + (size_t)q3.z * 32 + lane);
        float d0 = __ldg(&g_deg[q0.x]), d1 = __ldg(&g_deg[q0.z]);
        float d2 = __ldg(&g_deg[q1.x]), d3 = __ldg(&g_deg[q1.z]);
        float d4 = __ldg(&g_deg[q2.x]), d5 = __ldg(&g_deg[q2.z]);
        float d6 = __ldg(&g_deg[q3.x]), d7 = __ldg(&g_deg[q3.z]);
        float n0 = rsqrtf(d0) * __int_as_float(q0.y) * dc;
        float n1 = rsqrtf(d1) * __int_as_float(q0.w) * dc;
        float n2 = rsqrtf(d2) * __int_as_float(q1.y) * dc;
        float n3 = rsqrtf(d3) * __int_as_float(q1.w) * dc;
        float n4 = rsqrtf(d4) * __int_as_float(q2.y) * dc;
        float n5 = rsqrtf(d5) * __int_as_float(q2.w) * dc;
        float n6 = rsqrtf(d6) * __int_as_float(q3.y) * dc;
        float n7 = rsqrtf(d7) * __int_as_float(q3.w) * dc;
        unsigned long long m0 = pk2(n0, n0), m1 = pk2(n1, n1);
        unsigned long long m2 = pk2(n2, n2), m3 = pk2(n3, n3);
        unsigned long long m4 = pk2(n4, n4), m5 = pk2(n5, n5);
        unsigned long long m6 = pk2(n6, n6), m7 = pk2(n7, n7);
        ffma2(accA, v0.x, m0); ffma2(accB, v0.y, m0);
        ffma2(accA, v1.x, m1); ffma2(accB, v1.y, m1);
        ffma2(accA, v2.x, m2); ffma2(accB, v2.y, m2);
        ffma2(accA, v3.x, m3); ffma2(accB, v3.y, m3);
        ffma2(accA, v4.x, m4); ffma2(accB, v4.y, m4);
        ffma2(accA, v5.x, m5); ffma2(accB, v5.y, m5);
        ffma2(accA, v6.x, m6); ffma2(accB, v6.y, m6);
        ffma2(accA, v7.x, m7); ffma2(accB, v7.y, m7);
    }
    for (; p < cnt; p++) {
        int2 e0 = __ldg(ell + p);
        ulonglong2 v0 = __ldg(h2 + (size_t)e0.x * 32 + lane);
        float n0 = rsqrtf(__ldg(&g_deg[e0.x])) * __int_as_float(e0.y) * dc;
        unsigned long long m0 = pk2(n0, n0);
        ffma2(accA, v0.x, m0); ffma2(accB, v0.y, m0);
    }

    float2 fA = upk2(accA), fB = upk2(accB);
    float4 bb = ((const float4*)bias)[lane];
    float4 o;
    o.x = gelu_e(fA.x + bb.x);
    o.y = gelu_e(fA.y + bb.y);
    o.z = gelu_e(fB.x + bb.z);
    o.w = gelu_e(fB.y + bb.w);
    ((float4*)out)[(size_t)w * 32 + lane] = o;
}

extern "C" void kernel_launch(void* const* d_in, const int* in_sizes, int n_in,
                              void* d_out, int out_size) {
    const float* x   = (const float*)d_in[0];
    const void*  ei  = d_in[1];
    const float* ew  = (const float*)d_in[2];
    const float* W   = (const float*)d_in[3];
    const float* b   = (const float*)d_in[4];
    const float* lnw = (const float*)d_in[5];
    const float* lnb = (const float*)d_in[6];
    float* out = (float*)d_out;

    int n  = in_sizes[0] / DIM;         // 50000
    int E  = in_sizes[2];               // 800000
    int nb = (n + 255) / 256;
    int gemm_blocks = (n + 63) / 64;
    int deg_blocks  = (E + 255) / 256;

    k_f0       <<<nb, 256>>>(ei, W, n, in_sizes[1]);
    k_f1       <<<gemm_blocks + deg_blocks, 256>>>(x, lnw, lnb, n, ei, ew, E, gemm_blocks);
    k_aggregate<<<(n * 32 + 255) / 256, 256>>>(b, out, n);
}